// round 1
// baseline (speedup 1.0000x reference)
#include <cuda_runtime.h>
#include <cstdint>

// Problem constants (fixed by the dataset)
#define NN 50000
#define CC 64
#define OO 64
#define SS 8
#define KDIM 520          // S*C + S  (y flattened + qsum)

// ---------------- scratch (no cudaMalloc allowed) ----------------
__device__ float g_Y[(size_t)NN * KDIM];   // per-node accumulated [y(512) | qsum(8)]
__device__ float g_st[(size_t)NN * 16];    // [s(8) | t(8)] per node
__device__ int   g_off[NN + 1];            // CSR offsets from sorted dst

// ---------------- kernel 1: s/t projections ----------------
// st[i*16 + k] = x[i] @ Ws[:,k] + bs[k]   (k<8)
//             = x[i] @ Wt[:,k-8] + bt[k-8] (k>=8)
__global__ void st_kernel(const float* __restrict__ x,
                          const float* __restrict__ Ws, const float* __restrict__ bs,
                          const float* __restrict__ Wt, const float* __restrict__ bt,
                          float* __restrict__ st, int n) {
    __shared__ float sW[64][16];
    __shared__ float sb[16];
    int tid = threadIdx.x; // 256
    for (int idx = tid; idx < 512; idx += 256) {
        int c = idx >> 3, k = idx & 7;
        sW[c][k]     = Ws[idx];
        sW[c][8 + k] = Wt[idx];
    }
    if (tid < 8)  sb[tid]     = bs[tid];
    else if (tid < 16) sb[tid] = bt[tid - 8];
    __syncthreads();

    int i = blockIdx.x * 256 + tid;
    if (i >= n) return;

    float acc[16];
#pragma unroll
    for (int k = 0; k < 16; k++) acc[k] = sb[k];

    const float4* x4 = (const float4*)(x + (size_t)i * CC);
#pragma unroll
    for (int c4 = 0; c4 < 16; c4++) {
        float4 xv = x4[c4];
        int c = c4 * 4;
#pragma unroll
        for (int j = 0; j < 4; j++) {
            float xc = (j == 0) ? xv.x : (j == 1) ? xv.y : (j == 2) ? xv.z : xv.w;
            const float4* wr = (const float4*)&sW[c + j][0];
            float4 w0 = wr[0], w1 = wr[1], w2 = wr[2], w3 = wr[3];
            acc[0]  = fmaf(xc, w0.x, acc[0]);  acc[1]  = fmaf(xc, w0.y, acc[1]);
            acc[2]  = fmaf(xc, w0.z, acc[2]);  acc[3]  = fmaf(xc, w0.w, acc[3]);
            acc[4]  = fmaf(xc, w1.x, acc[4]);  acc[5]  = fmaf(xc, w1.y, acc[5]);
            acc[6]  = fmaf(xc, w1.z, acc[6]);  acc[7]  = fmaf(xc, w1.w, acc[7]);
            acc[8]  = fmaf(xc, w2.x, acc[8]);  acc[9]  = fmaf(xc, w2.y, acc[9]);
            acc[10] = fmaf(xc, w2.z, acc[10]); acc[11] = fmaf(xc, w2.w, acc[11]);
            acc[12] = fmaf(xc, w3.x, acc[12]); acc[13] = fmaf(xc, w3.y, acc[13]);
            acc[14] = fmaf(xc, w3.z, acc[14]); acc[15] = fmaf(xc, w3.w, acc[15]);
        }
    }
    float4* stout = (float4*)(st + (size_t)i * 16);
#pragma unroll
    for (int q = 0; q < 4; q++)
        stout[q] = make_float4(acc[q*4], acc[q*4+1], acc[q*4+2], acc[q*4+3]);
}

// ---------------- kernel 2: segment offsets from sorted dst ----------------
__global__ void offsets_kernel(const int* __restrict__ dst, int* __restrict__ off,
                               int E, int n) {
    int e = blockIdx.x * blockDim.x + threadIdx.x;
    if (e >= E) return;
    int d  = dst[e];
    int dp = (e == 0) ? -1 : dst[e - 1];
    for (int j = dp + 1; j <= d; j++) off[j] = e;
    if (e == E - 1)
        for (int j = d + 1; j <= n; j++) off[j] = E;
}

// ---------------- kernel 3: per-node edge aggregation ----------------
// warp per node i: Y[i, m*64+c] = sum_{e in seg(i)} q[e,m] * x[src[e], c]
//                  Y[i, 512+m]  = sum_e q[e,m]
__global__ void edge_kernel(const float* __restrict__ x, const int* __restrict__ src,
                            const float* __restrict__ st, const int* __restrict__ off,
                            float* __restrict__ Y, int n) {
    int gw   = (blockIdx.x * blockDim.x + threadIdx.x) >> 5;
    int lane = threadIdx.x & 31;
    if (gw >= n) return;
    int i = gw;
    int beg = off[i];
    int end = off[i + 1];

    float sreg = 0.f;
    if (lane < 8) sreg = st[(size_t)i * 16 + lane];

    float2 acc[8];
#pragma unroll
    for (int m = 0; m < 8; m++) acc[m] = make_float2(0.f, 0.f);
    float qs = 0.f;

    const float2* x2 = (const float2*)x;

    for (int e = beg; e < end; e++) {
        int sE = __ldg(&src[e]);
        float q = 0.f;
        if (lane < 8) {
            float l  = sreg + __ldg(&st[(size_t)sE * 16 + 8 + lane]);
            float ex = __expf(l);
            float tot = ex;
            tot += __shfl_xor_sync(0x000000ffu, tot, 1, 8);
            tot += __shfl_xor_sync(0x000000ffu, tot, 2, 8);
            tot += __shfl_xor_sync(0x000000ffu, tot, 4, 8);
            q = __fdividef(ex, tot);
            qs += q;
        }
        float2 xv = x2[(size_t)sE * 32 + lane];
#pragma unroll
        for (int m = 0; m < 8; m++) {
            float qm = __shfl_sync(0xffffffffu, q, m);
            acc[m].x = fmaf(qm, xv.x, acc[m].x);
            acc[m].y = fmaf(qm, xv.y, acc[m].y);
        }
    }

    float* Yrow = Y + (size_t)i * KDIM;
#pragma unroll
    for (int m = 0; m < 8; m++)
        ((float2*)(Yrow + m * 64))[lane] = acc[m];
    if (lane < 8) Yrow[512 + lane] = qs;
}

// ---------------- kernel 4: epilogue GEMM ----------------
// out[N,64] = Y[N,520] @ [W(512x64); b(8x64)] * 0.125
__global__ void gemm_kernel(const float* __restrict__ Y, const float* __restrict__ W,
                            const float* __restrict__ b, float* __restrict__ out, int n) {
    __shared__ float sA[8][128];
    __shared__ float sB[8][64];
    int tid = threadIdx.x;          // 256
    int tx = tid & 15;              // n-dir, 16 * 4 = 64
    int ty = tid >> 4;              // m-dir, 16 * 8 = 128
    int m0 = blockIdx.x * 128;

    float acc[8][4];
#pragma unroll
    for (int r = 0; r < 8; r++)
#pragma unroll
        for (int j = 0; j < 4; j++) acc[r][j] = 0.f;

    int arow = tid >> 1;
    int akq  = (tid & 1) * 4;
    int grow = m0 + arow;
    if (grow >= n) grow = n - 1;          // clamp (results discarded at store)
    const float4* Arow = (const float4*)(Y + (size_t)grow * KDIM);

    int bk = tid >> 5;                    // 0..7
    int bo = (tid & 31) * 2;              // 0..62

    for (int k0 = 0; k0 < KDIM; k0 += 8) {
        float4 av = Arow[(k0 + akq) >> 2];
        sA[akq + 0][arow] = av.x;
        sA[akq + 1][arow] = av.y;
        sA[akq + 2][arow] = av.z;
        sA[akq + 3][arow] = av.w;

        int kk = k0 + bk;
        const float* Bsrc = (kk < 512) ? (W + (size_t)kk * 64)
                                       : (b + (size_t)(kk - 512) * 64);
        float2 bv = *(const float2*)(Bsrc + bo);
        sB[bk][bo]     = bv.x;
        sB[bk][bo + 1] = bv.y;
        __syncthreads();

#pragma unroll
        for (int k = 0; k < 8; k++) {
            float4 a0 = *(const float4*)&sA[k][ty * 8];
            float4 a1 = *(const float4*)&sA[k][ty * 8 + 4];
            float4 bq = *(const float4*)&sB[k][tx * 4];
            float ar[8] = {a0.x, a0.y, a0.z, a0.w, a1.x, a1.y, a1.z, a1.w};
            float br[4] = {bq.x, bq.y, bq.z, bq.w};
#pragma unroll
            for (int r = 0; r < 8; r++)
#pragma unroll
                for (int j = 0; j < 4; j++)
                    acc[r][j] = fmaf(ar[r], br[j], acc[r][j]);
        }
        __syncthreads();
    }

#pragma unroll
    for (int r = 0; r < 8; r++) {
        int row = m0 + ty * 8 + r;
        if (row < n) {
            float4 v = make_float4(acc[r][0] * 0.125f, acc[r][1] * 0.125f,
                                   acc[r][2] * 0.125f, acc[r][3] * 0.125f);
            *(float4*)(out + (size_t)row * 64 + tx * 4) = v;
        }
    }
}

// ---------------- launch ----------------
extern "C" void kernel_launch(void* const* d_in, const int* in_sizes, int n_in,
                              void* d_out, int out_size) {
    const float* x   = (const float*)d_in[0];
    const int*   src = (const int*)d_in[1];
    const int*   dst = (const int*)d_in[2];
    const float* W   = (const float*)d_in[3];
    const float* b   = (const float*)d_in[4];
    const float* Ws  = (const float*)d_in[5];
    const float* bs  = (const float*)d_in[6];
    const float* Wt  = (const float*)d_in[7];
    const float* bt  = (const float*)d_in[8];
    float* out = (float*)d_out;

    int n = in_sizes[0] / CC;   // 50000
    int E = in_sizes[1];        // 1700000

    float* Y;  cudaGetSymbolAddress((void**)&Y,  g_Y);
    float* st; cudaGetSymbolAddress((void**)&st, g_st);
    int*  off; cudaGetSymbolAddress((void**)&off, g_off);

    st_kernel<<<(n + 255) / 256, 256>>>(x, Ws, bs, Wt, bt, st, n);
    offsets_kernel<<<(E + 255) / 256, 256>>>(dst, off, E, n);
    edge_kernel<<<(n * 32 + 255) / 256, 256>>>(x, src, st, off, Y, n);
    gemm_kernel<<<(n + 127) / 128, 256>>>(Y, W, b, out, n);
}